// round 2
// baseline (speedup 1.0000x reference)
#include <cuda_runtime.h>

#define NN 100000
#define EE 600000

// ---------------- scratch (static device globals; no runtime alloc) ----------
__device__ float g_bufA[NN * 128];
__device__ float g_bufB[NN * 128];
__device__ float g_ax[NN * 3];
__device__ int   g_cnt[NN];
__device__ int   g_rowptr[NN + 1];
__device__ int   g_cursor[NN];
__device__ float g_dis[NN];      // deg^-1/2 (deg includes self loop)
__device__ int   g_esrc[EE];     // CSR: source node per edge (grouped by target)
__device__ float g_ew[EE];       // CSR: norm weight per edge

// ---------------- graph preprocessing ----------------------------------------
__global__ void k_zero() {
    int i = blockIdx.x * blockDim.x + threadIdx.x;
    if (i < NN) g_cnt[i] = 0;
}

__global__ void k_hist(const int* __restrict__ ei) {
    int e = blockIdx.x * blockDim.x + threadIdx.x;
    if (e < EE) atomicAdd(&g_cnt[ei[EE + e]], 1);
}

// Single-block exclusive scan over 100k counts; also computes dis = rsqrt(deg).
__global__ void k_scan() {
    __shared__ int s[1024];
    int t = threadIdx.x;
    const int CH = (NN + 1023) / 1024;  // 98
    int base = t * CH;
    int sum = 0;
    for (int i = 0; i < CH; i++) {
        int idx = base + i;
        if (idx < NN) sum += g_cnt[idx];
    }
    s[t] = sum;
    __syncthreads();
    for (int off = 1; off < 1024; off <<= 1) {
        int v = (t >= off) ? s[t - off] : 0;
        __syncthreads();
        s[t] += v;
        __syncthreads();
    }
    int run = (t == 0) ? 0 : s[t - 1];
    for (int i = 0; i < CH; i++) {
        int idx = base + i;
        if (idx < NN) {
            int c = g_cnt[idx];
            g_rowptr[idx] = run;
            g_cursor[idx] = run;
            g_dis[idx] = rsqrtf((float)(c + 1));  // +1 self loop
            run += c;
        }
    }
    if (t == 1023) g_rowptr[NN] = run;
}

__global__ void k_fill(const int* __restrict__ ei) {
    int e = blockIdx.x * blockDim.x + threadIdx.x;
    if (e >= EE) return;
    int r = ei[e];
    int c = ei[EE + e];
    int p = atomicAdd(&g_cursor[c], 1);
    g_esrc[p] = r;
    g_ew[p] = g_dis[r] * g_dis[c];
}

// ---------------- aggregation kernels (gather, atomic-free) ------------------
// agg over raw x (3 features), thread per node
__global__ void k_agg0(const float* __restrict__ x) {
    int i = blockIdx.x * blockDim.x + threadIdx.x;
    if (i >= NN) return;
    float d = g_dis[i];
    float inv = d * d;
    float a0 = x[i * 3 + 0] * inv;
    float a1 = x[i * 3 + 1] * inv;
    float a2 = x[i * 3 + 2] * inv;
    int p1 = g_rowptr[i + 1];
    for (int p = g_rowptr[i]; p < p1; p++) {
        int s = g_esrc[p];
        float w = g_ew[p];
        a0 += w * x[s * 3 + 0];
        a1 += w * x[s * 3 + 1];
        a2 += w * x[s * 3 + 2];
    }
    g_ax[i * 3 + 0] = a0;
    g_ax[i * 3 + 1] = a1;
    g_ax[i * 3 + 2] = a2;
}

// F=128: warp per node, lane owns float4. reads g_bufB, writes g_bufA
__global__ void k_agg128() {
    int node = blockIdx.x * 8 + (threadIdx.x >> 5);
    if (node >= NN) return;
    int lane = threadIdx.x & 31;
    int off = lane * 4;
    float d = g_dis[node];
    float inv = d * d;
    float4 acc = *(const float4*)&g_bufB[node * 128 + off];
    acc.x *= inv; acc.y *= inv; acc.z *= inv; acc.w *= inv;
    int p1 = g_rowptr[node + 1];
    for (int p = g_rowptr[node]; p < p1; p++) {
        int s = g_esrc[p];
        float w = g_ew[p];
        float4 v = *(const float4*)&g_bufB[s * 128 + off];
        acc.x += w * v.x; acc.y += w * v.y; acc.z += w * v.z; acc.w += w * v.w;
    }
    *(float4*)&g_bufA[node * 128 + off] = acc;
}

// F=64: warp per node, lane owns float2. reads g_bufB, writes g_bufA
__global__ void k_agg64() {
    int node = blockIdx.x * 8 + (threadIdx.x >> 5);
    if (node >= NN) return;
    int lane = threadIdx.x & 31;
    int off = lane * 2;
    float d = g_dis[node];
    float inv = d * d;
    float2 acc = *(const float2*)&g_bufB[node * 64 + off];
    acc.x *= inv; acc.y *= inv;
    int p1 = g_rowptr[node + 1];
    for (int p = g_rowptr[node]; p < p1; p++) {
        int s = g_esrc[p];
        float w = g_ew[p];
        float2 v = *(const float2*)&g_bufB[s * 64 + off];
        acc.x += w * v.x; acc.y += w * v.y;
    }
    *(float2*)&g_bufA[node * 64 + off] = acc;
}

// final layer agg on 1 feature: out = b5 + Agg(s). reads g_bufB[N], writes d_out
__global__ void k_agg_out(float* __restrict__ out, const float* __restrict__ b5) {
    int i = blockIdx.x * blockDim.x + threadIdx.x;
    if (i >= NN) return;
    float d = g_dis[i];
    float acc = g_bufB[i] * d * d + b5[0];
    int p1 = g_rowptr[i + 1];
    for (int p = g_rowptr[i]; p < p1; p++)
        acc += g_ew[p] * g_bufB[g_esrc[p]];
    out[i] = acc;
}

// ---------------- GEMM kernels ------------------------------------------------
// Layer 1: H1 = relu(ax @ W1 + b1), K=3, M=128.  ax -> g_bufA
__global__ void k_gemm1(const float* __restrict__ W1, const float* __restrict__ b1) {
    __shared__ float ws[3 * 128];
    __shared__ float bs[128];
    for (int i = threadIdx.x; i < 384; i += 256) ws[i] = W1[i];
    if (threadIdx.x < 128) bs[threadIdx.x] = b1[threadIdx.x];
    __syncthreads();
    int gid = blockIdx.x * 256 + threadIdx.x;
    int row = gid >> 5;
    int c = (gid & 31) * 4;
    if (row >= NN) return;
    float a0 = g_ax[row * 3 + 0];
    float a1 = g_ax[row * 3 + 1];
    float a2 = g_ax[row * 3 + 2];
    float4 o;
    o.x = fmaxf(bs[c + 0] + a0 * ws[c + 0] + a1 * ws[128 + c + 0] + a2 * ws[256 + c + 0], 0.f);
    o.y = fmaxf(bs[c + 1] + a0 * ws[c + 1] + a1 * ws[128 + c + 1] + a2 * ws[256 + c + 1], 0.f);
    o.z = fmaxf(bs[c + 2] + a0 * ws[c + 2] + a1 * ws[128 + c + 2] + a2 * ws[256 + c + 2], 0.f);
    o.w = fmaxf(bs[c + 3] + a0 * ws[c + 3] + a1 * ws[128 + c + 3] + a2 * ws[256 + c + 3], 0.f);
    *(float4*)&g_bufA[row * 128 + c] = o;
}

// Main tiled GEMM: g_bufB[N,M] = f(g_bufA[N,K]) @ W[K,M]
// f = identity or relu(v + inb[k]) (folds previous layer's bias+relu).
// 256 threads; each thread: 4 rows x 16 cols (4 float4 col-groups strided 4*CG).
template <int K, int M, int TR, bool IN_T>
__global__ void __launch_bounds__(256) k_gemm(const float* __restrict__ W,
                                              const float* __restrict__ inb) {
    constexpr int CG = M / 16;       // col groups of 16
    constexpr int RG = 256 / CG;     // row groups
    constexpr int RT = TR / RG;      // rows per thread (== 4)
    static_assert(RT == 4, "rows per thread must be 4");
    extern __shared__ float sh[];
    float* Ws = sh;                  // K*M
    float* As = sh + K * M;          // K*TR, layout [k][r] (transposed tile)
    const int tid = threadIdx.x;
    const int rowBase = blockIdx.x * TR;

    for (int i = tid * 4; i < K * M; i += 1024)
        *(float4*)&Ws[i] = *(const float4*)&W[i];

    constexpr int K4 = K / 4;
    for (int idx = tid; idx < TR * K4; idx += 256) {
        int k4 = (idx / TR) * 4;
        int r = idx % TR;
        int gr = rowBase + r;
        float4 v = make_float4(0.f, 0.f, 0.f, 0.f);
        if (gr < NN) v = *(const float4*)&g_bufA[gr * K + k4];
        if (IN_T) {
            v.x = fmaxf(v.x + inb[k4 + 0], 0.f);
            v.y = fmaxf(v.y + inb[k4 + 1], 0.f);
            v.z = fmaxf(v.z + inb[k4 + 2], 0.f);
            v.w = fmaxf(v.w + inb[k4 + 3], 0.f);
        }
        As[(k4 + 0) * TR + r] = v.x;
        As[(k4 + 1) * TR + r] = v.y;
        As[(k4 + 2) * TR + r] = v.z;
        As[(k4 + 3) * TR + r] = v.w;
    }
    __syncthreads();

    const int cg = tid % CG;
    const int rg = tid / CG;
    const int r0 = rg * 4;
    const int c0 = cg * 4;

    float acc[4][16];
#pragma unroll
    for (int i = 0; i < 4; i++)
#pragma unroll
        for (int j = 0; j < 16; j++) acc[i][j] = 0.f;

#pragma unroll 8
    for (int k = 0; k < K; k++) {
        float4 a4 = *(const float4*)&As[k * TR + r0];
        float av[4] = {a4.x, a4.y, a4.z, a4.w};
        float wv[16];
#pragma unroll
        for (int j = 0; j < 4; j++) {
            float4 t = *(const float4*)&Ws[k * M + c0 + j * (4 * CG)];
            wv[j * 4 + 0] = t.x; wv[j * 4 + 1] = t.y;
            wv[j * 4 + 2] = t.z; wv[j * 4 + 3] = t.w;
        }
#pragma unroll
        for (int i = 0; i < 4; i++)
#pragma unroll
            for (int j = 0; j < 16; j++) acc[i][j] += av[i] * wv[j];
    }

#pragma unroll
    for (int i = 0; i < 4; i++) {
        int gr = rowBase + r0 + i;
        if (gr < NN) {
#pragma unroll
            for (int j = 0; j < 4; j++) {
                float4 o = make_float4(acc[i][j * 4 + 0], acc[i][j * 4 + 1],
                                       acc[i][j * 4 + 2], acc[i][j * 4 + 3]);
                *(float4*)&g_bufB[gr * M + c0 + j * (4 * CG)] = o;
            }
        }
    }
}

// Layer 5: s = relu(A4 + b4) @ W5 (K=64, M=1). g_bufA -> g_bufB[:,0]
__global__ void k_gemm5(const float* __restrict__ W5, const float* __restrict__ b4) {
    __shared__ float ws[64];
    __shared__ float bs[64];
    if (threadIdx.x < 64) {
        ws[threadIdx.x] = W5[threadIdx.x];
        bs[threadIdx.x] = b4[threadIdx.x];
    }
    __syncthreads();
    int row = blockIdx.x * blockDim.x + threadIdx.x;
    if (row >= NN) return;
    float acc = 0.f;
#pragma unroll
    for (int k = 0; k < 64; k++)
        acc += fmaxf(g_bufA[row * 64 + k] + bs[k], 0.f) * ws[k];
    g_bufB[row] = acc;
}

// ---------------- launcher ----------------------------------------------------
extern "C" void kernel_launch(void* const* d_in, const int* in_sizes, int n_in,
                              void* d_out, int out_size) {
    const float* x  = (const float*)d_in[0];
    const int*   ei = (const int*)d_in[1];
    const float* W1 = (const float*)d_in[2];
    const float* b1 = (const float*)d_in[3];
    const float* W2 = (const float*)d_in[4];
    const float* b2 = (const float*)d_in[5];
    const float* W3 = (const float*)d_in[6];
    const float* b3 = (const float*)d_in[7];
    const float* W4 = (const float*)d_in[8];
    const float* b4 = (const float*)d_in[9];
    const float* W5 = (const float*)d_in[10];
    const float* b5 = (const float*)d_in[11];
    float* out = (float*)d_out;

    // opt-in to large dynamic shared (idempotent; host-side, capture-safe)
    cudaFuncSetAttribute(k_gemm<128, 128, 128, false>,
                         cudaFuncAttributeMaxDynamicSharedMemorySize, 131072);
    cudaFuncSetAttribute(k_gemm<128, 64, 256, true>,
                         cudaFuncAttributeMaxDynamicSharedMemorySize, 163840);
    cudaFuncSetAttribute(k_gemm<64, 64, 256, true>,
                         cudaFuncAttributeMaxDynamicSharedMemorySize, 81920);

    const int NB_N = (NN + 255) / 256;   // 391
    const int NB_E = (EE + 255) / 256;   // 2344
    const int NB_W = (NN + 7) / 8;       // 12500 (warp per node)

    // graph preprocessing: CSR by target + symmetric norms
    k_zero<<<NB_N, 256>>>();
    k_hist<<<NB_E, 256>>>(ei);
    k_scan<<<1, 1024>>>();
    k_fill<<<NB_E, 256>>>(ei);

    // L1: aggregate x (3 feats) then GEMM 3->128 (+b1, relu)
    k_agg0<<<NB_N, 256>>>(x);
    k_gemm1<<<(NN * 32 + 255) / 256, 256>>>(W1, b1);

    // L2: T2 = H1 @ W2 ; A2 = Agg(T2)
    k_gemm<128, 128, 128, false><<<(NN + 127) / 128, 256, 131072>>>(W2, nullptr);
    k_agg128<<<NB_W, 256>>>();

    // L3: T3 = relu(A2 + b2) @ W3 ; A3 = Agg(T3)
    k_gemm<128, 64, 256, true><<<(NN + 255) / 256, 256, 163840>>>(W3, b2);
    k_agg64<<<NB_W, 256>>>();

    // L4: T4 = relu(A3 + b3) @ W4 ; A4 = Agg(T4)
    k_gemm<64, 64, 256, true><<<(NN + 255) / 256, 256, 81920>>>(W4, b3);
    k_agg64<<<NB_W, 256>>>();

    // L5: s = relu(A4 + b4) @ W5 ; out = Agg(s) + b5
    k_gemm5<<<NB_N, 256>>>(W5, b4);
    k_agg_out<<<NB_N, 256>>>(out, b5);
}

// round 4
// speedup vs baseline: 2.3318x; 2.3318x over previous
#include <cuda_runtime.h>
#include <cstdint>

#define NN 100000
#define EE 600000

// ---------------- scratch (static device globals; no runtime alloc) ----------
__device__ float g_bufA[NN * 128];
__device__ float g_bufB[NN * 128];
__device__ float g_ax[NN * 3];
__device__ int   g_cnt[NN];
__device__ int   g_rowptr[NN + 1];
__device__ int   g_cursor[NN];
__device__ float g_dis[NN];
__device__ int   g_esrc[EE];
__device__ float g_ew[EE];
__device__ int   g_bsum[98];
__device__ int   g_boff[98];

// ---------------- helpers ------------------------------------------------------
__device__ __forceinline__ uint32_t f2tf32(float f) {
    uint32_t u;
    asm("cvt.rna.tf32.f32 %0, %1;" : "=r"(u) : "f"(f));
    return u;
}
__device__ __forceinline__ void mma1688(float* c, const uint32_t* a, const uint32_t* b) {
    asm volatile(
        "mma.sync.aligned.m16n8k8.row.col.f32.tf32.tf32.f32 "
        "{%0,%1,%2,%3}, {%4,%5,%6,%7}, {%8,%9}, {%0,%1,%2,%3};"
        : "+f"(c[0]), "+f"(c[1]), "+f"(c[2]), "+f"(c[3])
        : "r"(a[0]), "r"(a[1]), "r"(a[2]), "r"(a[3]), "r"(b[0]), "r"(b[1]));
}

// ---------------- graph preprocessing ----------------------------------------
__global__ void k_zero() {
    int i = blockIdx.x * blockDim.x + threadIdx.x;
    if (i < NN) g_cnt[i] = 0;
}
__global__ void k_hist(const int* __restrict__ ei) {
    int e = blockIdx.x * blockDim.x + threadIdx.x;
    if (e < EE) atomicAdd(&g_cnt[ei[EE + e]], 1);
}
__global__ void k_scanA() {
    __shared__ int s[1024];
    int t = threadIdx.x;
    int i = blockIdx.x * 1024 + t;
    int v = (i < NN) ? g_cnt[i] : 0;
    s[t] = v;
    __syncthreads();
    for (int o = 512; o > 0; o >>= 1) {
        if (t < o) s[t] += s[t + o];
        __syncthreads();
    }
    if (t == 0) g_bsum[blockIdx.x] = s[0];
}
__global__ void k_scanB() {
    if (threadIdx.x == 0) {
        int run = 0;
        for (int b = 0; b < 98; b++) { g_boff[b] = run; run += g_bsum[b]; }
        g_rowptr[NN] = run;
    }
}
__global__ void k_scanC() {
    __shared__ int s[1024];
    int t = threadIdx.x;
    int i = blockIdx.x * 1024 + t;
    int v = (i < NN) ? g_cnt[i] : 0;
    s[t] = v;
    __syncthreads();
    for (int o = 1; o < 1024; o <<= 1) {
        int u = (t >= o) ? s[t - o] : 0;
        __syncthreads();
        s[t] += u;
        __syncthreads();
    }
    if (i < NN) {
        int excl = s[t] - v + g_boff[blockIdx.x];
        g_rowptr[i] = excl;
        g_cursor[i] = excl;
        g_dis[i] = rsqrtf((float)(v + 1));
    }
}
__global__ void k_fill(const int* __restrict__ ei) {
    int e = blockIdx.x * blockDim.x + threadIdx.x;
    if (e >= EE) return;
    int r = ei[e];
    int c = ei[EE + e];
    int p = atomicAdd(&g_cursor[c], 1);
    g_esrc[p] = r;
    g_ew[p] = g_dis[r] * g_dis[c];
}

// ---------------- aggregation kernels (gather, atomic-free) ------------------
__global__ void k_agg0(const float* __restrict__ x) {
    int i = blockIdx.x * blockDim.x + threadIdx.x;
    if (i >= NN) return;
    float d = g_dis[i];
    float inv = d * d;
    float a0 = x[i * 3 + 0] * inv;
    float a1 = x[i * 3 + 1] * inv;
    float a2 = x[i * 3 + 2] * inv;
    int p1 = g_rowptr[i + 1];
    for (int p = g_rowptr[i]; p < p1; p++) {
        int s = g_esrc[p];
        float w = g_ew[p];
        a0 += w * x[s * 3 + 0];
        a1 += w * x[s * 3 + 1];
        a2 += w * x[s * 3 + 2];
    }
    g_ax[i * 3 + 0] = a0;
    g_ax[i * 3 + 1] = a1;
    g_ax[i * 3 + 2] = a2;
}
__global__ void k_agg128() {
    int node = blockIdx.x * 8 + (threadIdx.x >> 5);
    if (node >= NN) return;
    int lane = threadIdx.x & 31;
    int off = lane * 4;
    float d = g_dis[node];
    float inv = d * d;
    float4 acc = *(const float4*)&g_bufB[node * 128 + off];
    acc.x *= inv; acc.y *= inv; acc.z *= inv; acc.w *= inv;
    int p1 = g_rowptr[node + 1];
    for (int p = g_rowptr[node]; p < p1; p++) {
        int s = g_esrc[p];
        float w = g_ew[p];
        float4 v = *(const float4*)&g_bufB[s * 128 + off];
        acc.x += w * v.x; acc.y += w * v.y; acc.z += w * v.z; acc.w += w * v.w;
    }
    *(float4*)&g_bufA[node * 128 + off] = acc;
}
__global__ void k_agg64() {
    int node = blockIdx.x * 8 + (threadIdx.x >> 5);
    if (node >= NN) return;
    int lane = threadIdx.x & 31;
    int off = lane * 2;
    float d = g_dis[node];
    float inv = d * d;
    float2 acc = *(const float2*)&g_bufB[node * 64 + off];
    acc.x *= inv; acc.y *= inv;
    int p1 = g_rowptr[node + 1];
    for (int p = g_rowptr[node]; p < p1; p++) {
        int s = g_esrc[p];
        float w = g_ew[p];
        float2 v = *(const float2*)&g_bufB[s * 64 + off];
        acc.x += w * v.x; acc.y += w * v.y;
    }
    *(float2*)&g_bufA[node * 64 + off] = acc;
}
__global__ void k_agg_out(float* __restrict__ out, const float* __restrict__ b5) {
    int i = blockIdx.x * blockDim.x + threadIdx.x;
    if (i >= NN) return;
    float d = g_dis[i];
    float acc = g_bufB[i] * d * d + b5[0];
    int p1 = g_rowptr[i + 1];
    for (int p = g_rowptr[i]; p < p1; p++)
        acc += g_ew[p] * g_bufB[g_esrc[p]];
    out[i] = acc;
}

// ---------------- small GEMMs (layers 1 and 5, SIMT) --------------------------
__global__ void k_gemm1(const float* __restrict__ W1, const float* __restrict__ b1) {
    __shared__ float ws[3 * 128];
    __shared__ float bs[128];
    for (int i = threadIdx.x; i < 384; i += 256) ws[i] = W1[i];
    if (threadIdx.x < 128) bs[threadIdx.x] = b1[threadIdx.x];
    __syncthreads();
    int gid = blockIdx.x * 256 + threadIdx.x;
    int row = gid >> 5;
    int c = (gid & 31) * 4;
    if (row >= NN) return;
    float a0 = g_ax[row * 3 + 0];
    float a1 = g_ax[row * 3 + 1];
    float a2 = g_ax[row * 3 + 2];
    float4 o;
    o.x = fmaxf(bs[c + 0] + a0 * ws[c + 0] + a1 * ws[128 + c + 0] + a2 * ws[256 + c + 0], 0.f);
    o.y = fmaxf(bs[c + 1] + a0 * ws[c + 1] + a1 * ws[128 + c + 1] + a2 * ws[256 + c + 1], 0.f);
    o.z = fmaxf(bs[c + 2] + a0 * ws[c + 2] + a1 * ws[128 + c + 2] + a2 * ws[256 + c + 2], 0.f);
    o.w = fmaxf(bs[c + 3] + a0 * ws[c + 3] + a1 * ws[128 + c + 3] + a2 * ws[256 + c + 3], 0.f);
    *(float4*)&g_bufA[row * 128 + c] = o;
}
__global__ void k_gemm5(const float* __restrict__ W5, const float* __restrict__ b4) {
    __shared__ float ws[64];
    __shared__ float bs[64];
    if (threadIdx.x < 64) {
        ws[threadIdx.x] = W5[threadIdx.x];
        bs[threadIdx.x] = b4[threadIdx.x];
    }
    __syncthreads();
    int row = blockIdx.x * blockDim.x + threadIdx.x;
    if (row >= NN) return;
    float acc = 0.f;
#pragma unroll
    for (int k = 0; k < 64; k++)
        acc += fmaxf(g_bufA[row * 64 + k] + bs[k], 0.f) * ws[k];
    g_bufB[row] = acc;
}

// ---------------- tf32 mma.sync GEMM (layers 2-4) -----------------------------
// g_bufB[N,M] = f(g_bufA[N,K]) @ W[K,M];  f = relu(v + inb) when IN_T.
// CTA: 128 rows x M cols, 256 threads = 8 warps in 4(m) x 2(n) grid.
// Warp tile: 32 x (M/2). mma.m16n8k8 tf32, fp32 accum.
template <int K, int M, bool IN_T>
__global__ void __launch_bounds__(256) k_tcgemm(const float* __restrict__ W,
                                                const float* __restrict__ inb) {
    constexpr int LDA = K + 4;          // padded row stride (floats)
    constexpr int LDB = M + 4;
    constexpr int NT = M / 16;          // n8-tiles per warp (8 or 4)
    extern __shared__ uint32_t sh[];
    uint32_t* As = sh;                  // [128][LDA]
    uint32_t* Bs = sh + 128 * LDA;      // [K][LDB]
    const int tid = threadIdx.x;
    const int rowBase = blockIdx.x * 128;

    // stage B = W (already [K][M] row-major), cvt to tf32
    constexpr int M4 = M / 4;
#pragma unroll 4
    for (int idx = tid; idx < K * M4; idx += 256) {
        int k = idx / M4;
        int n = (idx % M4) * 4;
        float4 v = *(const float4*)&W[k * M + n];
        uint4 u = make_uint4(f2tf32(v.x), f2tf32(v.y), f2tf32(v.z), f2tf32(v.w));
        *(uint4*)&Bs[k * LDB + n] = u;
    }
    // stage A rows (optional bias+relu fold), cvt to tf32
    constexpr int K4 = K / 4;
#pragma unroll 4
    for (int idx = tid; idx < 128 * K4; idx += 256) {
        int r = idx / K4;
        int kc = (idx % K4) * 4;
        int gr = rowBase + r;
        float4 v = make_float4(0.f, 0.f, 0.f, 0.f);
        if (gr < NN) v = *(const float4*)&g_bufA[gr * K + kc];
        if (IN_T) {
            v.x = fmaxf(v.x + inb[kc + 0], 0.f);
            v.y = fmaxf(v.y + inb[kc + 1], 0.f);
            v.z = fmaxf(v.z + inb[kc + 2], 0.f);
            v.w = fmaxf(v.w + inb[kc + 3], 0.f);
        }
        uint4 u = make_uint4(f2tf32(v.x), f2tf32(v.y), f2tf32(v.z), f2tf32(v.w));
        *(uint4*)&As[r * LDA + kc] = u;
    }
    __syncthreads();

    const int wid = tid >> 5;
    const int lane = tid & 31;
    const int g = lane >> 2;            // group id (0..7)
    const int tg = lane & 3;            // thread-in-group (0..3)
    const int mRow = (wid & 3) * 32;    // warp row base
    const int nCol = (wid >> 2) * (M / 2);

    float acc[2][NT][4];
#pragma unroll
    for (int mt = 0; mt < 2; mt++)
#pragma unroll
        for (int nt = 0; nt < NT; nt++)
#pragma unroll
            for (int i = 0; i < 4; i++) acc[mt][nt][i] = 0.f;

#pragma unroll
    for (int k0 = 0; k0 < K; k0 += 8) {
        uint32_t a[2][4];
#pragma unroll
        for (int mt = 0; mt < 2; mt++) {
            int r = mRow + mt * 16 + g;
            a[mt][0] = As[r * LDA + k0 + tg];
            a[mt][1] = As[(r + 8) * LDA + k0 + tg];
            a[mt][2] = As[r * LDA + k0 + tg + 4];
            a[mt][3] = As[(r + 8) * LDA + k0 + tg + 4];
        }
        uint32_t b[NT][2];
#pragma unroll
        for (int nt = 0; nt < NT; nt++) {
            int c = nCol + nt * 8 + g;
            b[nt][0] = Bs[(k0 + tg) * LDB + c];
            b[nt][1] = Bs[(k0 + tg + 4) * LDB + c];
        }
#pragma unroll
        for (int mt = 0; mt < 2; mt++)
#pragma unroll
            for (int nt = 0; nt < NT; nt++) mma1688(acc[mt][nt], a[mt], b[nt]);
    }

    // epilogue: c0,c1 at (row g, cols 2tg,2tg+1), c2,c3 at row g+8
#pragma unroll
    for (int mt = 0; mt < 2; mt++) {
        int r0 = rowBase + mRow + mt * 16 + g;
        int r1 = r0 + 8;
#pragma unroll
        for (int nt = 0; nt < NT; nt++) {
            int c = nCol + nt * 8 + 2 * tg;
            if (r0 < NN)
                *(float2*)&g_bufB[r0 * M + c] = make_float2(acc[mt][nt][0], acc[mt][nt][1]);
            if (r1 < NN)
                *(float2*)&g_bufB[r1 * M + c] = make_float2(acc[mt][nt][2], acc[mt][nt][3]);
        }
    }
}

// ---------------- launcher ----------------------------------------------------
extern "C" void kernel_launch(void* const* d_in, const int* in_sizes, int n_in,
                              void* d_out, int out_size) {
    const float* x  = (const float*)d_in[0];
    const int*   ei = (const int*)d_in[1];
    const float* W1 = (const float*)d_in[2];
    const float* b1 = (const float*)d_in[3];
    const float* W2 = (const float*)d_in[4];
    const float* b2 = (const float*)d_in[5];
    const float* W3 = (const float*)d_in[6];
    const float* b3 = (const float*)d_in[7];
    const float* W4 = (const float*)d_in[8];
    const float* b4 = (const float*)d_in[9];
    const float* W5 = (const float*)d_in[10];
    const float* b5 = (const float*)d_in[11];
    float* out = (float*)d_out;

    constexpr int SM2 = (128 * 132 + 128 * 132) * 4;  // 135168
    constexpr int SM3 = (128 * 132 + 128 * 68) * 4;   // 102400
    constexpr int SM4 = (128 * 68 + 64 * 68) * 4;     // 52224
    cudaFuncSetAttribute(k_tcgemm<128, 128, false>,
                         cudaFuncAttributeMaxDynamicSharedMemorySize, SM2);
    cudaFuncSetAttribute(k_tcgemm<128, 64, true>,
                         cudaFuncAttributeMaxDynamicSharedMemorySize, SM3);
    cudaFuncSetAttribute(k_tcgemm<64, 64, true>,
                         cudaFuncAttributeMaxDynamicSharedMemorySize, SM4);

    const int NB_N = (NN + 255) / 256;
    const int NB_E = (EE + 255) / 256;
    const int NB_W = (NN + 7) / 8;
    const int GB   = (NN + 127) / 128;  // 782 GEMM tiles

    // graph preprocessing: CSR by target + symmetric norms
    k_zero<<<NB_N, 256>>>();
    k_hist<<<NB_E, 256>>>(ei);
    k_scanA<<<98, 1024>>>();
    k_scanB<<<1, 32>>>();
    k_scanC<<<98, 1024>>>();
    k_fill<<<NB_E, 256>>>(ei);

    // L1: aggregate x (3 feats), GEMM 3->128 (+b1, relu)
    k_agg0<<<NB_N, 256>>>(x);
    k_gemm1<<<(NN * 32 + 255) / 256, 256>>>(W1, b1);

    // L2: T2 = H1 @ W2 (tf32 mma.sync) ; A2 = Agg(T2)
    k_tcgemm<128, 128, false><<<GB, 256, SM2>>>(W2, nullptr);
    k_agg128<<<NB_W, 256>>>();

    // L3: T3 = relu(A2 + b2) @ W3 ; A3 = Agg(T3)
    k_tcgemm<128, 64, true><<<GB, 256, SM3>>>(W3, b2);
    k_agg64<<<NB_W, 256>>>();

    // L4: T4 = relu(A3 + b3) @ W4 ; A4 = Agg(T4)
    k_tcgemm<64, 64, true><<<GB, 256, SM4>>>(W4, b3);
    k_agg64<<<NB_W, 256>>>();

    // L5: s = relu(A4 + b4) @ W5 ; out = Agg(s) + b5
    k_gemm5<<<NB_N, 256>>>(W5, b4);
    k_agg_out<<<NB_N, 256>>>(out, b5);
}